// round 1
// baseline (speedup 1.0000x reference)
#include <cuda_runtime.h>

// Problem constants
#define BB   2048
#define DD   256
#define OUTN 256
#define KK   16
#define DKN  (DD * KK)   // 4096

// Scratch (device globals; no allocation allowed)
__device__ float g_Vt[DKN * OUTN];    // [dk][out] = values^T + g_k * skip_w^T  (4 MB)
__device__ float g_SWt[DD * OUTN];    // [d][out]  = skip_w^T                   (256 KB)

// grid = linspace(-1, 1, 16) in fp32 (matches jnp.linspace to ~1 ulp; the
// interpolation is continuous across bucket boundaries so ulp-level bucket
// disagreements change the result by O(1e-7)).
__constant__ float c_grid[16] = {
    -1.0f,         -0.86666667f, -0.73333333f, -0.6f,
    -0.46666667f,  -0.33333334f, -0.2f,        -0.06666667f,
     0.06666667f,   0.2f,         0.33333333f,  0.46666667f,
     0.6f,          0.73333333f,  0.86666667f,  1.0f
};

// ---------------------------------------------------------------------------
// Kernel 1: transpose skip_w (OUT, D) -> g_SWt (D, OUT)
// ---------------------------------------------------------------------------
__global__ void k_transpose_skip(const float* __restrict__ sw) {
    __shared__ float tile[32][33];
    int tx = threadIdx.x, ty = threadIdx.y;
    int dbase = blockIdx.x * 32;   // D tile
    int obase = blockIdx.y * 32;   // OUT tile
#pragma unroll
    for (int i = 0; i < 32; i += 8)
        tile[ty + i][tx] = sw[(obase + ty + i) * DD + dbase + tx];
    __syncthreads();
#pragma unroll
    for (int i = 0; i < 32; i += 8)
        g_SWt[(dbase + ty + i) * OUTN + obase + tx] = tile[tx][ty + i];
}

// ---------------------------------------------------------------------------
// Kernel 2: build Vt[dk][out] = values[out][dk] + grid[k] * skip_w[out][d]
// (pure 256x4096 transpose with a fused skip-fold epilogue)
// ---------------------------------------------------------------------------
__global__ void k_build_vt(const float* __restrict__ vals) {
    __shared__ float tile[32][33];
    int tx = threadIdx.x, ty = threadIdx.y;
    int dkbase = blockIdx.x * 32;  // DK tile
    int obase  = blockIdx.y * 32;  // OUT tile
#pragma unroll
    for (int i = 0; i < 32; i += 8)
        tile[ty + i][tx] = vals[(obase + ty + i) * DKN + dkbase + tx];
    __syncthreads();
#pragma unroll
    for (int i = 0; i < 32; i += 8) {
        int dk  = dkbase + ty + i;
        int out = obase + tx;
        int k = dk & 15;
        int d = dk >> 4;
        g_Vt[dk * OUTN + out] = tile[tx][ty + i] + c_grid[k] * g_SWt[d * OUTN + out];
    }
}

// ---------------------------------------------------------------------------
// Kernel 3: main spline-gather kernel.
// Block: 128 threads handles BTILE=8 rows of x and all 256 outputs.
//   og = tid & 63  -> outputs [4*og, 4*og+3] (float4)
//   bg = tid >> 6  -> b rows  [bg*4, bg*4+3]
// Phase 1: compute packed (l + w) per (b, d) into shared.
// Phase 2: for each d, gather Vt[d][l][out4] / Vt[d][l+1][out4] and FMA.
// ---------------------------------------------------------------------------
__global__ __launch_bounds__(128) void k_main(const float* __restrict__ x,
                                              const float* __restrict__ skip_b,
                                              float* __restrict__ y) {
    __shared__ float s_lw[8 * 256];
    const int tid = threadIdx.x;
    const int b0 = blockIdx.x * 8;

    // Phase 1: bucketize (matches searchsorted(grid, xc, side='left') semantics)
#pragma unroll
    for (int it = 0; it < 16; ++it) {
        int idx = tid + it * 128;          // 0..2047
        int bi = idx >> 8;
        int d  = idx & 255;
        float xv = x[(b0 + bi) * DD + d];
        float xc = fminf(fmaxf(xv, -1.0f), 1.0f);
        float t = (xc + 1.0f) * 7.5f;
        int j = (int)t;
        if (j > 14) j = 14;
        if (j > 0 && xc <= c_grid[j]) {
            --j;                            // xc lands exactly on (or under) left edge
        } else if (j < 14 && xc > c_grid[j + 1]) {
            ++j;                            // fp-rounding safety
        }
        float w = (xc - c_grid[j]) / (c_grid[j + 1] - c_grid[j]);
        w = fminf(fmaxf(w, 0.0f), 1.0f);
        // pack l+w; clamp so decoded l <= 14 always
        s_lw[idx] = fminf((float)j + w, 14.999999f);
    }
    __syncthreads();

    const int og = tid & 63;
    const int bg = tid >> 6;               // 0 or 1
    const float* vbase = g_Vt + og * 4;
    const float* slw = s_lw + bg * 4 * 256;

    float4 acc0 = make_float4(0.f, 0.f, 0.f, 0.f);
    float4 acc1 = acc0, acc2 = acc0, acc3 = acc0;

#pragma unroll 1
    for (int d = 0; d < 256; ++d) {
        const float* vd = vbase + d * (KK * OUTN);

#define PROC(ci, ACC)                                                          \
        {                                                                      \
            float val = slw[(ci) * 256 + d];                                   \
            float fl = floorf(val);                                            \
            int l = (int)fl;                                                   \
            float w = val - fl;                                                \
            const float* p = vd + l * OUTN;                                    \
            float4 vl = *(const float4*)(p);                                   \
            float4 vr = *(const float4*)(p + OUTN);                            \
            float f0 = 1.0f - w;                                               \
            ACC.x = fmaf(f0, vl.x, fmaf(w, vr.x, ACC.x));                      \
            ACC.y = fmaf(f0, vl.y, fmaf(w, vr.y, ACC.y));                      \
            ACC.z = fmaf(f0, vl.z, fmaf(w, vr.z, ACC.z));                      \
            ACC.w = fmaf(f0, vl.w, fmaf(w, vr.w, ACC.w));                      \
        }

        PROC(0, acc0)
        PROC(1, acc1)
        PROC(2, acc2)
        PROC(3, acc3)
#undef PROC
    }

    // Epilogue: add bias, store
    float4 sb = *(const float4*)(skip_b + og * 4);
    float4 r0 = make_float4(acc0.x + sb.x, acc0.y + sb.y, acc0.z + sb.z, acc0.w + sb.w);
    float4 r1 = make_float4(acc1.x + sb.x, acc1.y + sb.y, acc1.z + sb.z, acc1.w + sb.w);
    float4 r2 = make_float4(acc2.x + sb.x, acc2.y + sb.y, acc2.z + sb.z, acc2.w + sb.w);
    float4 r3 = make_float4(acc3.x + sb.x, acc3.y + sb.y, acc3.z + sb.z, acc3.w + sb.w);

    int brow = b0 + bg * 4;
    *(float4*)(y + (brow + 0) * OUTN + og * 4) = r0;
    *(float4*)(y + (brow + 1) * OUTN + og * 4) = r1;
    *(float4*)(y + (brow + 2) * OUTN + og * 4) = r2;
    *(float4*)(y + (brow + 3) * OUTN + og * 4) = r3;
}

// ---------------------------------------------------------------------------
extern "C" void kernel_launch(void* const* d_in, const int* in_sizes, int n_in,
                              void* d_out, int out_size) {
    const float* x      = (const float*)d_in[0];  // (B, D)
    const float* values = (const float*)d_in[1];  // (OUT, D, K)
    const float* skip_w = (const float*)d_in[2];  // (OUT, D)
    const float* skip_b = (const float*)d_in[3];  // (OUT,)
    float* y = (float*)d_out;                     // (B, OUT)

    dim3 t(32, 8);
    k_transpose_skip<<<dim3(DD / 32, OUTN / 32), t>>>(skip_w);
    k_build_vt<<<dim3(DKN / 32, OUTN / 32), t>>>(values);
    k_main<<<BB / 8, 128>>>(x, skip_b, y);
}

// round 2
// speedup vs baseline: 1.4711x; 1.4711x over previous
#include <cuda_runtime.h>

// Problem constants
#define BB   2048
#define DD   256
#define OUTN 256
#define KK   16
#define DKN  (DD * KK)   // 4096

// Main-kernel tiling
#define BTILE   64
#define OTILE   32
#define NTHR    256
#define NSTAGE  4
#define LWS     66                         // padded lw row stride (floats), 8B-aligned
#define LW_FLOATS  (DD * LWS)              // 16896
#define TAB_FLOATS (NSTAGE * KK * OTILE)   // 2048
#define SMEM_BYTES ((LW_FLOATS + TAB_FLOATS) * 4)

// Scratch (device globals; no allocation allowed)
__device__ float g_Vt[DKN * OUTN];    // [d][k][out] = values^T + g_k * skip_w^T  (4 MB)
__device__ float g_SWt[DD * OUTN];    // [d][out]  = skip_w^T

__constant__ float c_grid[16] = {
    -1.0f,         -0.86666667f, -0.73333333f, -0.6f,
    -0.46666667f,  -0.33333334f, -0.2f,        -0.06666667f,
     0.06666667f,   0.2f,         0.33333333f,  0.46666667f,
     0.6f,          0.73333333f,  0.86666667f,  1.0f
};

// ---------------------------------------------------------------------------
// Kernel 1: transpose skip_w (OUT, D) -> g_SWt (D, OUT)
// ---------------------------------------------------------------------------
__global__ void k_transpose_skip(const float* __restrict__ sw) {
    __shared__ float tile[32][33];
    int tx = threadIdx.x, ty = threadIdx.y;
    int dbase = blockIdx.x * 32;
    int obase = blockIdx.y * 32;
#pragma unroll
    for (int i = 0; i < 32; i += 8)
        tile[ty + i][tx] = sw[(obase + ty + i) * DD + dbase + tx];
    __syncthreads();
#pragma unroll
    for (int i = 0; i < 32; i += 8)
        g_SWt[(dbase + ty + i) * OUTN + obase + tx] = tile[tx][ty + i];
}

// ---------------------------------------------------------------------------
// Kernel 2: build Vt[dk][out] = values[out][dk] + grid[k] * skip_w[out][d]
// (folds the skip connection into the spline table: hat-basis interp of a
//  linear function on its own grid is exact)
// ---------------------------------------------------------------------------
__global__ void k_build_vt(const float* __restrict__ vals) {
    __shared__ float tile[32][33];
    int tx = threadIdx.x, ty = threadIdx.y;
    int dkbase = blockIdx.x * 32;
    int obase  = blockIdx.y * 32;
#pragma unroll
    for (int i = 0; i < 32; i += 8)
        tile[ty + i][tx] = vals[(obase + ty + i) * DKN + dkbase + tx];
    __syncthreads();
#pragma unroll
    for (int i = 0; i < 32; i += 8) {
        int dk  = dkbase + ty + i;
        int out = obase + tx;
        int k = dk & 15;
        int d = dk >> 4;
        g_Vt[dk * OUTN + out] = tile[tx][ty + i] + c_grid[k] * g_SWt[d * OUTN + out];
    }
}

// ---------------------------------------------------------------------------
// Kernel 3: smem-staged spline gather.
// Block: 256 threads, BTILE=64 b-rows x OTILE=32 outs, loops over all 256 d.
//   Phase 1: compute packed (l + w) per (b, d) into smem s_lw[d][b] (pad 66).
//   Main loop: cp.async-pipeline the 16x32 table slice for each d into a
//   4-stage smem ring; every thread gathers (v_l, v_r) float4s from smem.
//   Thread map: og = tid & 7 (out quad), bg = tid >> 3 (pair of b-rows).
//   Each LDS.128 quarter-warp phase = 8 og threads reading one contiguous
//   128B table row -> conflict-free.
// ---------------------------------------------------------------------------
__device__ __forceinline__ void cp_tab_stage(float* s_tab, int d, int o0, int tid) {
    if (tid < 128) {
        int k = tid >> 3;
        int j = (tid & 7) * 4;
        const float* src = g_Vt + ((d * KK + k) << 8) + o0 + j;
        float* dst = s_tab + (d & (NSTAGE - 1)) * (KK * OTILE) + k * OTILE + j;
        unsigned saddr = (unsigned)__cvta_generic_to_shared(dst);
        asm volatile("cp.async.cg.shared.global [%0], [%1], 16;\n"
                     :: "r"(saddr), "l"(src) : "memory");
    }
}

__global__ __launch_bounds__(NTHR) void k_main(const float* __restrict__ x,
                                               const float* __restrict__ skip_b,
                                               float* __restrict__ y) {
    extern __shared__ float smem[];
    float* s_lw  = smem;               // [256][66]
    float* s_tab = smem + LW_FLOATS;   // [4][16][32]

    const int tid = threadIdx.x;
    const int b0 = (blockIdx.x >> 3) * BTILE;
    const int o0 = (blockIdx.x & 7) * OTILE;

    // ---- Phase 1: bucketize (identical semantics to validated R1 kernel) ----
#pragma unroll 4
    for (int it = 0; it < BTILE; ++it) {
        // all 256 threads read row (b0+it), coalesced; d = tid
        float xv = x[(b0 + it) * DD + tid];
        float xc = fminf(fmaxf(xv, -1.0f), 1.0f);
        float t = (xc + 1.0f) * 7.5f;
        int j = (int)t;
        if (j > 14) j = 14;
        if (j > 0 && xc <= c_grid[j]) {
            --j;
        } else if (j < 14 && xc > c_grid[j + 1]) {
            ++j;
        }
        float w = (xc - c_grid[j]) / (c_grid[j + 1] - c_grid[j]);
        w = fminf(fmaxf(w, 0.0f), 1.0f);
        s_lw[tid * LWS + it] = fminf((float)j + w, 14.999999f);
    }

    // ---- Prologue: prefetch stages 0..2 ----
#pragma unroll
    for (int p = 0; p < NSTAGE - 1; ++p) {
        cp_tab_stage(s_tab, p, o0, tid);
        asm volatile("cp.async.commit_group;\n" ::: "memory");
    }
    __syncthreads();   // covers phase-1 s_lw visibility too

    const int og = tid & 7;
    const int bg = tid >> 3;   // 0..31 -> b-rows {2bg, 2bg+1}

    float4 accA = make_float4(0.f, 0.f, 0.f, 0.f);
    float4 accB = accA;

#pragma unroll 4
    for (int d = 0; d < DD; ++d) {
        asm volatile("cp.async.wait_group 2;\n" ::: "memory");
        __syncthreads();  // stage d%4 visible to all; stage (d-1)%4 free to refill

        if (d + NSTAGE - 1 < DD)
            cp_tab_stage(s_tab, d + NSTAGE - 1, o0, tid);
        asm volatile("cp.async.commit_group;\n" ::: "memory");

        const float* tb = s_tab + (d & (NSTAGE - 1)) * (KK * OTILE);
        float2 lwp = *(const float2*)&s_lw[d * LWS + 2 * bg];

        // b-row A
        {
            float fl = floorf(lwp.x);
            float w = lwp.x - fl;
            int l = (int)fl;
            const float4* p = (const float4*)(tb + l * OTILE) + og;
            float4 vl = p[0];
            float4 vr = p[OTILE / 4];   // next k row
            float f0 = 1.0f - w;
            accA.x = fmaf(f0, vl.x, fmaf(w, vr.x, accA.x));
            accA.y = fmaf(f0, vl.y, fmaf(w, vr.y, accA.y));
            accA.z = fmaf(f0, vl.z, fmaf(w, vr.z, accA.z));
            accA.w = fmaf(f0, vl.w, fmaf(w, vr.w, accA.w));
        }
        // b-row B
        {
            float fl = floorf(lwp.y);
            float w = lwp.y - fl;
            int l = (int)fl;
            const float4* p = (const float4*)(tb + l * OTILE) + og;
            float4 vl = p[0];
            float4 vr = p[OTILE / 4];
            float f0 = 1.0f - w;
            accB.x = fmaf(f0, vl.x, fmaf(w, vr.x, accB.x));
            accB.y = fmaf(f0, vl.y, fmaf(w, vr.y, accB.y));
            accB.z = fmaf(f0, vl.z, fmaf(w, vr.z, accB.z));
            accB.w = fmaf(f0, vl.w, fmaf(w, vr.w, accB.w));
        }
    }

    // ---- Epilogue: add bias, store ----
    float4 sb = *(const float4*)(skip_b + o0 + og * 4);
    float4 rA = make_float4(accA.x + sb.x, accA.y + sb.y, accA.z + sb.z, accA.w + sb.w);
    float4 rB = make_float4(accB.x + sb.x, accB.y + sb.y, accB.z + sb.z, accB.w + sb.w);

    int brow = b0 + 2 * bg;
    *(float4*)(y + (brow + 0) * OUTN + o0 + og * 4) = rA;
    *(float4*)(y + (brow + 1) * OUTN + o0 + og * 4) = rB;
}

// ---------------------------------------------------------------------------
extern "C" void kernel_launch(void* const* d_in, const int* in_sizes, int n_in,
                              void* d_out, int out_size) {
    const float* x      = (const float*)d_in[0];  // (B, D)
    const float* values = (const float*)d_in[1];  // (OUT, D, K)
    const float* skip_w = (const float*)d_in[2];  // (OUT, D)
    const float* skip_b = (const float*)d_in[3];  // (OUT,)
    float* y = (float*)d_out;                     // (B, OUT)

    cudaFuncSetAttribute(k_main, cudaFuncAttributeMaxDynamicSharedMemorySize,
                         SMEM_BYTES);

    dim3 t(32, 8);
    k_transpose_skip<<<dim3(DD / 32, OUTN / 32), t>>>(skip_w);
    k_build_vt<<<dim3(DKN / 32, OUTN / 32), t>>>(values);
    k_main<<<(BB / BTILE) * (OUTN / OTILE), NTHR, SMEM_BYTES>>>(x, skip_b, y);
}

// round 3
// speedup vs baseline: 1.4732x; 1.0014x over previous
#include <cuda_runtime.h>

// Problem constants
#define BB   2048
#define DD   256
#define OUTN 256
#define KK   16
#define DKN  (DD * KK)   // 4096

// Main-kernel tiling
#define BTILE   32
#define OTILE   32
#define NTHR    256
#define DCHUNK  8                            // d-slices per pipeline stage
#define NCHUNK  (DD / DCHUNK)                // 32
#define CHUNK_FLOATS (DCHUNK * KK * OTILE)   // 4096
#define LWS     34                           // padded lw row stride (floats)
#define LW_FLOATS  (DD * LWS)                // 8704
#define SMEM_BYTES ((LW_FLOATS + 2 * CHUNK_FLOATS) * 4)   // 67,584 B -> 3 blocks/SM

// Scratch (device global; no allocation allowed)
__device__ float g_Vt[DKN * OUTN];    // [d][k][out] = values^T + g_k * skip_w^T  (4 MB)

__constant__ float c_grid[16] = {
    -1.0f,         -0.86666667f, -0.73333333f, -0.6f,
    -0.46666667f,  -0.33333334f, -0.2f,        -0.06666667f,
     0.06666667f,   0.2f,         0.33333333f,  0.46666667f,
     0.6f,          0.73333333f,  0.86666667f,  1.0f
};

// ---------------------------------------------------------------------------
// Kernel 1: build Vt[d][k][out] = values[out][d][k] + grid[k] * skip_w[out][d]
// Pure 256x4096 transpose with fused skip-fold (hat-basis interp of a linear
// function on its own grid is exact, so the skip connection folds into the
// table). skip_w read transposed via a tiny smem tile.
// ---------------------------------------------------------------------------
__global__ void k_build_vt(const float* __restrict__ vals,
                           const float* __restrict__ sw) {
    __shared__ float tile[32][33];
    __shared__ float s_sw[2][32];    // [d - d0][o - o0]; 32 dk span exactly 2 d
    int tx = threadIdx.x, ty = threadIdx.y;
    int dkbase = blockIdx.x * 32;
    int obase  = blockIdx.y * 32;
    int d0 = dkbase >> 4;

    if (ty < 2)
        s_sw[ty][tx] = sw[(obase + tx) * DD + d0 + ty];
#pragma unroll
    for (int i = 0; i < 32; i += 8)
        tile[ty + i][tx] = vals[(obase + ty + i) * DKN + dkbase + tx];
    __syncthreads();
#pragma unroll
    for (int i = 0; i < 32; i += 8) {
        int dk = dkbase + ty + i;
        int k  = dk & 15;
        int dl = (dk >> 4) - d0;     // 0 or 1
        g_Vt[dk * OUTN + obase + tx] = tile[tx][ty + i] + c_grid[k] * s_sw[dl][tx];
    }
}

// ---------------------------------------------------------------------------
// Kernel 2: smem-staged spline gather, chunked double-buffered pipeline.
// Block: 256 threads, BTILE=32 b-rows x OTILE=32 outs.
//   og = tid & 7  -> outs [o0 + 4*og, +3] (float4)
//   bg = tid >> 3 -> b-row b0 + bg (one per thread)
// Phase 1: packed (l + w) per (b, d) into s_lw[d][b].
// Main loop: 32 chunks of 8 d's; each chunk's 16KB table slice cp.async'd
// into a 2-stage ring; one wait+barrier per chunk; inner 8-d loop sync-free.
// ---------------------------------------------------------------------------
__device__ __forceinline__ void cp_chunk(float* s_tab, int c, int o0, int tid) {
    int d0k = c * DCHUNK;
    float* dstbase = s_tab + (c & 1) * CHUNK_FLOATS;
#pragma unroll
    for (int r = 0; r < 4; ++r) {
        int lin  = (r * NTHR + tid) * 4;          // float offset in chunk
        int doff = lin >> 9;                      // /512 (16k x 32o per d)
        int win  = lin & 511;
        int k    = win >> 5;
        int j    = win & 31;
        const float* src = g_Vt + (((d0k + doff) * KK + k) << 8) + o0 + j;
        unsigned saddr = (unsigned)__cvta_generic_to_shared(dstbase + lin);
        asm volatile("cp.async.cg.shared.global [%0], [%1], 16;\n"
                     :: "r"(saddr), "l"(src) : "memory");
    }
}

__global__ __launch_bounds__(NTHR) void k_main(const float* __restrict__ x,
                                               const float* __restrict__ skip_b,
                                               float* __restrict__ y) {
    extern __shared__ float smem[];
    float* s_lw  = smem;               // [256][34]
    float* s_tab = smem + LW_FLOATS;   // [2][8][16][32]

    const int tid = threadIdx.x;
    const int b0 = (blockIdx.x >> 3) * BTILE;
    const int o0 = (blockIdx.x & 7) * OTILE;

    // ---- Prologue: prefetch chunk 0 (overlaps phase-1 LDGs) ----
    cp_chunk(s_tab, 0, o0, tid);
    asm volatile("cp.async.commit_group;\n" ::: "memory");

    // ---- Phase 1: bucketize (validated semantics) ----
#pragma unroll 4
    for (int it = 0; it < BTILE; ++it) {
        float xv = x[(b0 + it) * DD + tid];      // coalesced; d = tid
        float xc = fminf(fmaxf(xv, -1.0f), 1.0f);
        float t = (xc + 1.0f) * 7.5f;
        int j = (int)t;
        if (j > 14) j = 14;
        if (j > 0 && xc <= c_grid[j]) {
            --j;
        } else if (j < 14 && xc > c_grid[j + 1]) {
            ++j;
        }
        float w = (xc - c_grid[j]) / (c_grid[j + 1] - c_grid[j]);
        w = fminf(fmaxf(w, 0.0f), 1.0f);
        s_lw[tid * LWS + it] = fminf((float)j + w, 14.999999f);
    }

    const int og = tid & 7;
    const int bg = tid >> 3;
    float4 acc = make_float4(0.f, 0.f, 0.f, 0.f);

#pragma unroll 1
    for (int c = 0; c < NCHUNK; ++c) {
        asm volatile("cp.async.wait_group 0;\n" ::: "memory");
        __syncthreads();   // chunk c visible; all warps done with buf (c+1)&1

        if (c + 1 < NCHUNK) {
            cp_chunk(s_tab, c + 1, o0, tid);
            asm volatile("cp.async.commit_group;\n" ::: "memory");
        }

        const float* tb_base = s_tab + (c & 1) * CHUNK_FLOATS;
        const float* lwp = s_lw + (c * DCHUNK) * LWS + bg;

#pragma unroll
        for (int dd = 0; dd < DCHUNK; ++dd) {
            float val = lwp[dd * LWS];
            float fl = floorf(val);
            int l = (int)fl;
            float w = val - fl;
            const float4* p = (const float4*)(tb_base + dd * (KK * OTILE) + l * OTILE) + og;
            float4 vl = p[0];
            float4 vr = p[OTILE / 4];   // next k row
            float f0 = 1.0f - w;
            acc.x = fmaf(f0, vl.x, fmaf(w, vr.x, acc.x));
            acc.y = fmaf(f0, vl.y, fmaf(w, vr.y, acc.y));
            acc.z = fmaf(f0, vl.z, fmaf(w, vr.z, acc.z));
            acc.w = fmaf(f0, vl.w, fmaf(w, vr.w, acc.w));
        }
    }

    // ---- Epilogue: add bias, store ----
    float4 sb = *(const float4*)(skip_b + o0 + og * 4);
    float4 r = make_float4(acc.x + sb.x, acc.y + sb.y, acc.z + sb.z, acc.w + sb.w);
    *(float4*)(y + (b0 + bg) * OUTN + o0 + og * 4) = r;
}

// ---------------------------------------------------------------------------
extern "C" void kernel_launch(void* const* d_in, const int* in_sizes, int n_in,
                              void* d_out, int out_size) {
    const float* x      = (const float*)d_in[0];  // (B, D)
    const float* values = (const float*)d_in[1];  // (OUT, D, K)
    const float* skip_w = (const float*)d_in[2];  // (OUT, D)
    const float* skip_b = (const float*)d_in[3];  // (OUT,)
    float* y = (float*)d_out;                     // (B, OUT)

    cudaFuncSetAttribute(k_main, cudaFuncAttributeMaxDynamicSharedMemorySize,
                         SMEM_BYTES);

    k_build_vt<<<dim3(DKN / 32, OUTN / 32), dim3(32, 8)>>>(values, skip_w);
    k_main<<<(BB / BTILE) * (OUTN / OTILE), NTHR, SMEM_BYTES>>>(x, skip_b, y);
}

// round 4
// speedup vs baseline: 2.0464x; 1.3890x over previous
#include <cuda_runtime.h>

// Problem constants
#define BB   2048
#define DD   256
#define OUTN 256
#define KK   16
#define DKN  (DD * KK)   // 4096

// Main-kernel tiling
#define BTILE   32
#define OTILE   32
#define NTHR    256
#define DCHUNK  8                            // d-slices per pipeline stage
#define NCHUNK  (DD / DCHUNK)                // 32
#define CHUNK_FLOATS (DCHUNK * KK * OTILE)   // 4096 floats = 16KB
#define LWROW   33                           // padded lw row stride (floats)
#define LWB     (DCHUNK * LWROW)             // 264 floats per lw buffer
#define NLWBUF  4
#define SMEM_BYTES ((2 * CHUNK_FLOATS + NLWBUF * LWB) * 4)   // ~37KB -> 4+ blocks/SM

// Scratch (device global; no allocation allowed)
__device__ float g_Vt[DKN * OUTN];    // [d][k][out] = values^T + g_k * skip_w^T  (4 MB)

__constant__ float c_grid[16] = {
    -1.0f,         -0.86666667f, -0.73333333f, -0.6f,
    -0.46666667f,  -0.33333334f, -0.2f,        -0.06666667f,
     0.06666667f,   0.2f,         0.33333333f,  0.46666667f,
     0.6f,          0.73333333f,  0.86666667f,  1.0f
};

// ---------------------------------------------------------------------------
// Kernel 1: build Vt[d][k][out] = values[out][d][k] + grid[k] * skip_w[out][d]
// (hat-basis interpolation of a linear function on its own grid is exact, so
//  the skip connection folds into the table)
// ---------------------------------------------------------------------------
__global__ void k_build_vt(const float* __restrict__ vals,
                           const float* __restrict__ sw) {
    __shared__ float tile[32][33];
    __shared__ float s_sw[2][32];    // 32 dk span exactly 2 d
    int tx = threadIdx.x, ty = threadIdx.y;
    int dkbase = blockIdx.x * 32;
    int obase  = blockIdx.y * 32;
    int d0 = dkbase >> 4;

    if (ty < 2)
        s_sw[ty][tx] = sw[(obase + tx) * DD + d0 + ty];
#pragma unroll
    for (int i = 0; i < 32; i += 8)
        tile[ty + i][tx] = vals[(obase + ty + i) * DKN + dkbase + tx];
    __syncthreads();
#pragma unroll
    for (int i = 0; i < 32; i += 8) {
        int dk = dkbase + ty + i;
        int k  = dk & 15;
        int dl = (dk >> 4) - d0;
        g_Vt[dk * OUTN + obase + tx] = tile[tx][ty + i] + c_grid[k] * s_sw[dl][tx];
    }
}

// ---------------------------------------------------------------------------
// Kernel 2: smem-staged spline gather.
// Block: 256 threads, BTILE=32 b x OTILE=32 outs; 32 chunks of 8 d's.
//   og = tid & 7  -> outs [o0+4og .. +3] (float4);  bg = tid >> 3 -> b-row.
// Table slices cp.async'd into a 2-stage ring; (l+w) computed on the fly
// into a 4-deep 1KB ring (no big s_lw). One barrier per chunk.
// LDS.128 gathers conflict-free: each quarter-warp phase (8 og lanes, one bg)
// reads one contiguous 128B table row.
// ---------------------------------------------------------------------------
__device__ __forceinline__ void cp_chunk(float* s_tab, int c, int o0, int tid) {
    float* dstbase = s_tab + (c & 1) * CHUNK_FLOATS;
    int d0k = c * DCHUNK;
#pragma unroll
    for (int r = 0; r < 4; ++r) {
        int lin  = (r * NTHR + tid) * 4;          // float offset in chunk
        int doff = lin >> 9;                      // 512 floats per d-slice
        int win  = lin & 511;
        int k    = win >> 5;
        int j    = win & 31;
        const float* src = g_Vt + (((d0k + doff) * KK + k) << 8) + o0 + j;
        unsigned saddr = (unsigned)__cvta_generic_to_shared(dstbase + lin);
        asm volatile("cp.async.cg.shared.global [%0], [%1], 16;\n"
                     :: "r"(saddr), "l"(src) : "memory");
    }
}

// Bucketize x for chunk c: thread (dd = tid&7, bi = tid>>3) handles one (b,d).
__device__ __forceinline__ void compute_lw(float* s_lw, const float* __restrict__ x,
                                           int b0, int c, int tid) {
    int dd = tid & 7;
    int bi = tid >> 3;
    float xv = x[(b0 + bi) * DD + c * DCHUNK + dd];
    float xc = fminf(fmaxf(xv, -1.0f), 1.0f);
    float t = (xc + 1.0f) * 7.5f;
    int j = (int)t;
    if (j > 14) j = 14;
    if (j > 0 && xc <= c_grid[j]) {
        --j;
    } else if (j < 14 && xc > c_grid[j + 1]) {
        ++j;
    }
    float w = (xc - c_grid[j]) / (c_grid[j + 1] - c_grid[j]);
    w = fminf(fmaxf(w, 0.0f), 1.0f);
    s_lw[(c & (NLWBUF - 1)) * LWB + dd * LWROW + bi] =
        fminf((float)j + w, 14.999999f);
}

__global__ __launch_bounds__(NTHR, 4) void k_main(const float* __restrict__ x,
                                                  const float* __restrict__ skip_b,
                                                  float* __restrict__ y) {
    extern __shared__ float smem[];
    float* s_tab = smem;                         // [2][8][16][32]
    float* s_lw  = smem + 2 * CHUNK_FLOATS;      // [4][8][33]

    const int tid = threadIdx.x;
    const int b0 = (blockIdx.x >> 3) * BTILE;
    const int o0 = (blockIdx.x & 7) * OTILE;

    // ---- Prologue ----
    cp_chunk(s_tab, 0, o0, tid);
    asm volatile("cp.async.commit_group;\n" ::: "memory");
    compute_lw(s_lw, x, b0, 0, tid);
    compute_lw(s_lw, x, b0, 1, tid);

    const int og = tid & 7;
    const int bg = tid >> 3;
    float4 acc = make_float4(0.f, 0.f, 0.f, 0.f);

#pragma unroll 1
    for (int c = 0; c < NCHUNK; ++c) {
        asm volatile("cp.async.wait_group 0;\n" ::: "memory");
        __syncthreads();   // tab[c] + lw[c] visible; tab[(c+1)&1] & lw[(c+2)&3] free

        if (c + 1 < NCHUNK) {
            cp_chunk(s_tab, c + 1, o0, tid);
            asm volatile("cp.async.commit_group;\n" ::: "memory");
        }
        if (c + 2 < NCHUNK)
            compute_lw(s_lw, x, b0, c + 2, tid);

        const float* tb = s_tab + (c & 1) * CHUNK_FLOATS;
        const float* lw = s_lw + (c & (NLWBUF - 1)) * LWB + bg;

#pragma unroll
        for (int dd = 0; dd < DCHUNK; dd += 4) {
            float4 vl[4], vr[4];
            float  w[4];
#pragma unroll
            for (int j2 = 0; j2 < 4; ++j2) {
                float val = lw[(dd + j2) * LWROW];
                float fl = floorf(val);
                int l = (int)fl;
                w[j2] = val - fl;
                const float4* p =
                    (const float4*)(tb + (dd + j2) * (KK * OTILE) + l * OTILE) + og;
                vl[j2] = p[0];
                vr[j2] = p[OTILE / 4];
            }
#pragma unroll
            for (int j2 = 0; j2 < 4; ++j2) {
                float f0 = 1.0f - w[j2];
                acc.x = fmaf(f0, vl[j2].x, fmaf(w[j2], vr[j2].x, acc.x));
                acc.y = fmaf(f0, vl[j2].y, fmaf(w[j2], vr[j2].y, acc.y));
                acc.z = fmaf(f0, vl[j2].z, fmaf(w[j2], vr[j2].z, acc.z));
                acc.w = fmaf(f0, vl[j2].w, fmaf(w[j2], vr[j2].w, acc.w));
            }
        }
    }

    // ---- Epilogue: add bias, store ----
    float4 sb = *(const float4*)(skip_b + o0 + og * 4);
    float4 r = make_float4(acc.x + sb.x, acc.y + sb.y, acc.z + sb.z, acc.w + sb.w);
    *(float4*)(y + (b0 + bg) * OUTN + o0 + og * 4) = r;
}

// ---------------------------------------------------------------------------
extern "C" void kernel_launch(void* const* d_in, const int* in_sizes, int n_in,
                              void* d_out, int out_size) {
    const float* x      = (const float*)d_in[0];  // (B, D)
    const float* values = (const float*)d_in[1];  // (OUT, D, K)
    const float* skip_w = (const float*)d_in[2];  // (OUT, D)
    const float* skip_b = (const float*)d_in[3];  // (OUT,)
    float* y = (float*)d_out;                     // (B, OUT)

    cudaFuncSetAttribute(k_main, cudaFuncAttributeMaxDynamicSharedMemorySize,
                         SMEM_BYTES);

    k_build_vt<<<dim3(DKN / 32, OUTN / 32), dim3(32, 8)>>>(values, skip_w);
    k_main<<<(BB / BTILE) * (OUTN / OTILE), NTHR, SMEM_BYTES>>>(x, skip_b, y);
}